// round 7
// baseline (speedup 1.0000x reference)
#include <cuda_runtime.h>
#include <cstdint>
#include <math.h>

#define DIM   768
#define HID   3072
#define HID2  1536
#define NLEV  9
#define SEQ   2048
#define MROWS 4096
#define EPSLN 1e-5f

#define BM 128
#define BN 128
#define BK 48
#define NT 256
#define MAX_TILES 48

#define ASTR 52    /* 48 data + 4 pad floats: 16B aligned, 8-row bank-bijective */
#define BSTR 136   /* B rows: 128 data + 8 pad floats */
#define ABUF (BM*ASTR)   /* 6656 floats */
#define BBUF (BK*BSTR)   /* 6528 floats */
#define STAGE (ABUF+BBUF)
#define NSTAGE 2
#define SMEM_FLOATS (NSTAGE*STAGE)
#define SMEM_BYTES  (SMEM_FLOATS*4)   /* 105472 B */

#define MID_MAIN_BLKS (6*32)   /* gemm2_main tiles */
#define MID_BLKS (MID_MAIN_BLKS + 12*MAX_TILES)

// ---------------- scratch (no allocations allowed) ----------------
__device__ float g_xnorm[MROWS*DIM];
__device__ float g_h[(size_t)MROWS*HID];
__device__ float g_main[MROWS*DIM];
__device__ float g_hl[MROWS*HID2];
__device__ float g_W1r[DIM*HID];
__device__ float g_W2r[HID*DIM];
__device__ float g_A1r[NLEV*DIM*HID2];
__device__ float g_A2r[NLEV*HID2*DIM];
__device__ float g_mix[SEQ];
__device__ int   g_depth[SEQ];
__device__ int   g_rowperm[MROWS];
__device__ int   g_sched_lvl[MAX_TILES];
__device__ int   g_sched_start[MAX_TILES];
__device__ int   g_sched_rows[MAX_TILES];
__device__ int   g_ntiles;

// ---------------- PTX helpers ----------------
__device__ __forceinline__ uint32_t smem_u32(const void* p) {
    return (uint32_t)__cvta_generic_to_shared(p);
}
__device__ __forceinline__ void cp16(uint32_t dst, const void* src) {
    asm volatile("cp.async.cg.shared.global [%0], [%1], 16;" :: "r"(dst), "l"(src));
}
__device__ __forceinline__ void cp_commit() {
    asm volatile("cp.async.commit_group;" ::: "memory");
}
__device__ __forceinline__ void cp_wait0() {
    asm volatile("cp.async.wait_group 0;" ::: "memory");
}
__device__ __forceinline__ uint32_t f2tf32(float x) {
    uint32_t r;
    asm("cvt.rna.tf32.f32 %0, %1;" : "=r"(r) : "f"(x));
    return r;
}
__device__ __forceinline__ float round_tf32f(float x) {
    return __uint_as_float(f2tf32(x));
}
__device__ __forceinline__ void ldsm_x4(uint32_t& r0, uint32_t& r1, uint32_t& r2, uint32_t& r3,
                                        uint32_t addr) {
    asm volatile("ldmatrix.sync.aligned.m8n8.x4.shared.b16 {%0,%1,%2,%3}, [%4];"
                 : "=r"(r0), "=r"(r1), "=r"(r2), "=r"(r3) : "r"(addr));
}
__device__ __forceinline__ void mma_tf32(float& c0, float& c1, float& c2, float& c3,
                                         uint32_t a0, uint32_t a1, uint32_t a2, uint32_t a3,
                                         uint32_t b0, uint32_t b1) {
    asm volatile(
        "mma.sync.aligned.m16n8k8.row.col.f32.tf32.tf32.f32 "
        "{%0,%1,%2,%3}, {%4,%5,%6,%7}, {%8,%9}, {%0,%1,%2,%3};"
        : "+f"(c0), "+f"(c1), "+f"(c2), "+f"(c3)
        : "r"(a0), "r"(a1), "r"(a2), "r"(a3), "r"(b0), "r"(b1));
}

// ---------------- weight rounding: all four weight tensors in one launch ----------------
#define N4_W (DIM*HID/4)
#define N4_A (NLEV*DIM*HID2/4)
#define N4_TOTAL (2*N4_W + 2*N4_A)
__global__ void __launch_bounds__(256) round_all(const float4* __restrict__ W1,
                                                 const float4* __restrict__ W2,
                                                 const float4* __restrict__ A1,
                                                 const float4* __restrict__ A2) {
    int i = blockIdx.x*256 + threadIdx.x;
    if (i >= N4_TOTAL) return;
    const float4* src; float4* dst;
    if (i < N4_W)            { src = W1 + i;                dst = (float4*)g_W1r + i; }
    else if (i < 2*N4_W)     { src = W2 + (i - N4_W);       dst = (float4*)g_W2r + (i - N4_W); }
    else if (i < 2*N4_W+N4_A){ src = A1 + (i - 2*N4_W);     dst = (float4*)g_A1r + (i - 2*N4_W); }
    else                     { src = A2 + (i - 2*N4_W-N4_A);dst = (float4*)g_A2r + (i - 2*N4_W-N4_A); }
    float4 v = *src;
    v.x = round_tf32f(v.x); v.y = round_tf32f(v.y);
    v.z = round_tf32f(v.z); v.w = round_tf32f(v.w);
    *dst = v;
}

// ---------------- prep: depth clip, counting sort, tile schedule, mix ----------------
__global__ void prep_kernel(const int* __restrict__ levels, const float* __restrict__ lmw) {
    __shared__ int cnt[NLEV];
    __shared__ int cursor[NLEV];
    __shared__ float denom_sh;
    int t = threadIdx.x;
    if (t < NLEV) cnt[t] = 0;
    __syncthreads();
    for (int s = t; s < SEQ; s += NT) {
        int d = levels[s*4];
        d = min(max(d, 0), NLEV-1);
        g_depth[s] = d;
        atomicAdd(&cnt[d], 1);
    }
    __syncthreads();
    if (t == 0) {
        int o = 0, tile = 0;
        float denom = 0.f;
        for (int l = 0; l < NLEV; ++l) {
            cursor[l] = o;
            int rows = 2*cnt[l];
            int nt2 = (rows + BM - 1)/BM;
            for (int i = 0; i < nt2 && tile < MAX_TILES; ++i) {
                g_sched_lvl[tile]   = l;
                g_sched_start[tile] = o + i*BM;
                g_sched_rows[tile]  = min(BM, rows - i*BM);
                ++tile;
            }
            o += rows;
            denom += (float)cnt[l] * expf(lmw[l]);
        }
        for (int i = tile; i < MAX_TILES; ++i) g_sched_rows[i] = 0;
        g_ntiles = tile;
        denom_sh = denom;
    }
    __syncthreads();
    for (int r = t; r < MROWS; r += NT) {
        int s = r & (SEQ-1);
        int d = g_depth[s];
        int pos = atomicAdd(&cursor[d], 1);
        g_rowperm[pos] = r;
    }
    float denom = denom_sh;
    for (int s = t; s < SEQ; s += NT)
        g_mix[s] = expf(lmw[g_depth[s]]) / denom;
}

// ---------------- layernorm (writes tf32-rounded output) ----------------
__global__ void __launch_bounds__(256) ln_kernel(const float* __restrict__ x,
                                                 const float* __restrict__ gamma,
                                                 const float* __restrict__ beta) {
    int row = blockIdx.x;
    int t = threadIdx.x;
    const float* xr = x + (size_t)row*DIM;
    float v0 = xr[t], v1 = xr[t+256], v2 = xr[t+512];
    float s  = v0+v1+v2;
    float sq = v0*v0 + v1*v1 + v2*v2;
    __shared__ float red0[8], red1[8], mv[2];
#pragma unroll
    for (int o = 16; o > 0; o >>= 1) {
        s  += __shfl_xor_sync(0xffffffffu, s,  o);
        sq += __shfl_xor_sync(0xffffffffu, sq, o);
    }
    int wid = t >> 5, lid = t & 31;
    if (lid == 0) { red0[wid] = s; red1[wid] = sq; }
    __syncthreads();
    if (t == 0) {
        float S = 0.f, SQ = 0.f;
#pragma unroll
        for (int i = 0; i < 8; ++i) { S += red0[i]; SQ += red1[i]; }
        float mean = S * (1.0f/DIM);
        float var  = SQ * (1.0f/DIM) - mean*mean;
        mv[0] = mean; mv[1] = rsqrtf(var + EPSLN);
    }
    __syncthreads();
    float mean = mv[0], inv = mv[1];
    float* o = g_xnorm + (size_t)row*DIM;
    o[t]     = round_tf32f((v0-mean)*inv*gamma[t]     + beta[t]);
    o[t+256] = round_tf32f((v1-mean)*inv*gamma[t+256] + beta[t+256]);
    o[t+512] = round_tf32f((v2-mean)*inv*gamma[t+512] + beta[t+512]);
}

// ---------------- chunk loader: A (gathered rows, 48 floats) + B (48 x 128) ----------------
__device__ __forceinline__ void load_chunk(const float* __restrict__ A, int lda,
                                           const float* __restrict__ B, int ldb,
                                           int n0, int k0,
                                           const int* __restrict__ rowidx,
                                           float* As, float* Bs) {
    int t = threadIdx.x;
    // A: 128 rows x 48 floats; 2 threads per row, 6 cp16 each
    int arow = t >> 1, ahalf = (t & 1)*6;
    const float* asrc = A + (size_t)rowidx[arow]*lda + k0 + ahalf*4;
    uint32_t adst = smem_u32(As + arow*ASTR + ahalf*4);
#pragma unroll
    for (int j = 0; j < 6; ++j)
        cp16(adst + j*16, asrc + j*4);
    // B: 48 rows x 128 floats; 1536 cp16 over 6 iters
#pragma unroll
    for (int i = 0; i < 6; ++i) {
        int ci = t + i*NT;
        int k = ci >> 5, ns = ci & 31;
        cp16(smem_u32(Bs + k*BSTR + ns*4),
             B + (size_t)(k0+k)*ldb + n0 + ns*4);
    }
}

// ---------------- mma mainloop: 2-stage double buffer, ldmatrix A, scalar-LDS B ----------------
__device__ __forceinline__ void mma_mainloop(const float* __restrict__ A, int lda,
                                             const float* __restrict__ B, int ldb,
                                             int K, int n0,
                                             const int* __restrict__ rowidx,
                                             float* smem, float acc[4][4][4]) {
    int t = threadIdx.x;
    int wid = t >> 5, lane = t & 31;
    int wm = wid & 1, wn = wid >> 1;
    int qid = lane >> 2, qtr = lane & 3;

    // ldmatrix lane address pattern (per mt), byte offsets within A stage
    int l8 = lane & 7, lhi = (lane >> 3) & 1, lk = lane >> 4;
    uint32_t a_off[4];
#pragma unroll
    for (int mt = 0; mt < 4; ++mt) {
        int row = wm*64 + mt*16 + lhi*8 + l8;
        a_off[mt] = (uint32_t)((row*ASTR + lk*4) * 4);
    }

    int nch = K / BK;
    load_chunk(A, lda, B, ldb, n0, 0, rowidx, smem, smem + ABUF);
    cp_commit();

    for (int c = 0; c < nch; ++c) {
        cp_wait0();          // chunk c resident
        __syncthreads();     // all warps done with buffer (c+1)&1 from iter c-1
        if (c + 1 < nch) {
            int st = (c + 1) & 1;
            load_chunk(A, lda, B, ldb, n0, (c+1)*BK, rowidx,
                       smem + st*STAGE, smem + st*STAGE + ABUF);
            cp_commit();     // overlaps the compute below
        }
        const float* Ab = smem + (c & 1)*STAGE;
        const float* Bb = Ab + ABUF;
        uint32_t ab_base = smem_u32(Ab);
#pragma unroll
        for (int ks = 0; ks < 6; ++ks) {
            int k0 = ks * 8;
            uint32_t af[4][4], bf[4][2];
#pragma unroll
            for (int mt = 0; mt < 4; ++mt)
                ldsm_x4(af[mt][0], af[mt][1], af[mt][2], af[mt][3],
                        ab_base + a_off[mt] + (uint32_t)(k0*4));
#pragma unroll
            for (int nt = 0; nt < 4; ++nt) {
                int cc = wn*32 + nt*8 + qid;
                bf[nt][0] = __float_as_uint(Bb[(k0 + qtr    )*BSTR + cc]);
                bf[nt][1] = __float_as_uint(Bb[(k0 + qtr + 4)*BSTR + cc]);
            }
#pragma unroll
            for (int mt = 0; mt < 4; ++mt)
#pragma unroll
                for (int nt = 0; nt < 4; ++nt)
                    mma_tf32(acc[mt][nt][0], acc[mt][nt][1],
                             acc[mt][nt][2], acc[mt][nt][3],
                             af[mt][0], af[mt][1], af[mt][2], af[mt][3],
                             bf[nt][0], bf[nt][1]);
        }
    }
}

__device__ __forceinline__ float gelu_exact(float v) {
    return 0.5f * v * (1.0f + erff(v * 0.70710678118654752f));
}

// ---------------- main MLP GEMM1: h = round(gelu(xnorm @ W1 + b1)) ----------------
__global__ void __launch_bounds__(NT, 2) k_gemm1_main(const float* __restrict__ b1) {
    extern __shared__ float smem[];
    __shared__ int s_row[BM];
    int t = threadIdx.x;
    int m0 = blockIdx.y * BM, n0 = blockIdx.x * BN;
    if (t < BM) s_row[t] = m0 + t;
    __syncthreads();
    float acc[4][4][4] = {};
    mma_mainloop(g_xnorm, DIM, g_W1r, HID, DIM, n0, s_row, smem, acc);
    int wid = t >> 5, lane = t & 31;
    int wm = wid & 1, wn = wid >> 1, qid = lane >> 2, qtr = lane & 3;
#pragma unroll
    for (int mt = 0; mt < 4; ++mt) {
        int r0 = m0 + wm*64 + mt*16 + qid;
#pragma unroll
        for (int nt = 0; nt < 4; ++nt) {
            int col = n0 + wn*32 + nt*8 + qtr*2;
            float bx = b1[col], by = b1[col+1];
            *(float2*)(g_h + (size_t)r0*HID + col) =
                make_float2(round_tf32f(gelu_exact(acc[mt][nt][0]+bx)),
                            round_tf32f(gelu_exact(acc[mt][nt][1]+by)));
            *(float2*)(g_h + (size_t)(r0+8)*HID + col) =
                make_float2(round_tf32f(gelu_exact(acc[mt][nt][2]+bx)),
                            round_tf32f(gelu_exact(acc[mt][nt][3]+by)));
        }
    }
}

// ---------------- fused mid kernel: gemm2_main tiles + gemm1_adapt tiles ----------------
__global__ void __launch_bounds__(NT, 2) k_mid(const float* __restrict__ b2,
                                               const float* __restrict__ a1b) {
    extern __shared__ float smem[];
    __shared__ int s_row[BM];
    int t = threadIdx.x;
    int bid = blockIdx.x;
    int wid = t >> 5, lane = t & 31;
    int wm = wid & 1, wn = wid >> 1, qid = lane >> 2, qtr = lane & 3;

    if (bid < MID_MAIN_BLKS) {
        // ---- main = g_h @ W2r + b2 ----
        int m0 = (bid / 6) * BM, n0 = (bid % 6) * BN;
        if (t < BM) s_row[t] = m0 + t;
        __syncthreads();
        float acc[4][4][4] = {};
        mma_mainloop(g_h, HID, g_W2r, DIM, HID, n0, s_row, smem, acc);
#pragma unroll
        for (int mt = 0; mt < 4; ++mt) {
            int r0 = m0 + wm*64 + mt*16 + qid;
#pragma unroll
            for (int nt = 0; nt < 4; ++nt) {
                int col = n0 + wn*32 + nt*8 + qtr*2;
                float bx = b2[col], by = b2[col+1];
                *(float2*)(g_main + (size_t)r0*DIM + col) =
                    make_float2(acc[mt][nt][0]+bx, acc[mt][nt][1]+by);
                *(float2*)(g_main + (size_t)(r0+8)*DIM + col) =
                    make_float2(acc[mt][nt][2]+bx, acc[mt][nt][3]+by);
            }
        }
    } else {
        // ---- hl = round(relu(xnorm[perm] @ A1r[lvl] + a1b[lvl])) ----
        int b2i = bid - MID_MAIN_BLKS;
        int tile = b2i / 12;
        if (tile >= g_ntiles) return;
        int n0 = (b2i % 12) * BN;
        int lvl = g_sched_lvl[tile], start = g_sched_start[tile], rows = g_sched_rows[tile];
        if (t < BM) s_row[t] = g_rowperm[start + min(t, rows-1)];
        __syncthreads();
        float acc[4][4][4] = {};
        mma_mainloop(g_xnorm, DIM, g_A1r + (size_t)lvl*DIM*HID2, HID2, DIM, n0,
                     s_row, smem, acc);
        const float* bb = a1b + (size_t)lvl*HID2;
#pragma unroll
        for (int mt = 0; mt < 4; ++mt) {
            int ml = wm*64 + mt*16 + qid;
#pragma unroll
            for (int nt = 0; nt < 4; ++nt) {
                int col = n0 + wn*32 + nt*8 + qtr*2;
                float bx = bb[col], by = bb[col+1];
                if (ml < rows)
                    *(float2*)(g_hl + (size_t)(start+ml)*HID2 + col) =
                        make_float2(round_tf32f(fmaxf(acc[mt][nt][0]+bx, 0.f)),
                                    round_tf32f(fmaxf(acc[mt][nt][1]+by, 0.f)));
                if (ml+8 < rows)
                    *(float2*)(g_hl + (size_t)(start+ml+8)*HID2 + col) =
                        make_float2(round_tf32f(fmaxf(acc[mt][nt][2]+bx, 0.f)),
                                    round_tf32f(fmaxf(acc[mt][nt][3]+by, 0.f)));
            }
        }
    }
}

// ---------------- adapter GEMM2 + final combine ----------------
__global__ void __launch_bounds__(NT, 2) k_gemm2_adapt(const float* __restrict__ a2b,
                                                       float* __restrict__ out) {
    if ((int)blockIdx.y >= g_ntiles) return;
    extern __shared__ float smem[];
    __shared__ int s_row[BM];
    int t = threadIdx.x;
    int tile = blockIdx.y;
    int lvl = g_sched_lvl[tile], start = g_sched_start[tile], rows = g_sched_rows[tile];
    int n0 = blockIdx.x * BN;
    if (t < BM) s_row[t] = min(start + t, MROWS-1);   // g_hl rows are compacted
    __syncthreads();
    float acc[4][4][4] = {};
    mma_mainloop(g_hl, HID2, g_A2r + (size_t)lvl*HID2*DIM, DIM, HID2, n0, s_row, smem, acc);
    int wid = t >> 5, lane = t & 31;
    int wm = wid & 1, wn = wid >> 1, qid = lane >> 2, qtr = lane & 3;
    const float* bb = a2b + (size_t)lvl*DIM;
#pragma unroll
    for (int mt = 0; mt < 4; ++mt) {
        int ml = wm*64 + mt*16 + qid;
#pragma unroll
        for (int nt = 0; nt < 4; ++nt) {
            int col = n0 + wn*32 + nt*8 + qtr*2;
            float bx = bb[col], by = bb[col+1];
            if (ml < rows) {
                int r = g_rowperm[start + ml];
                float mix = g_mix[r & (SEQ-1)];
                const float* mp = g_main + (size_t)r*DIM + col;
                *(float2*)(out + (size_t)r*DIM + col) =
                    make_float2(mp[0]*(1.f-mix) + (acc[mt][nt][0]+bx)*mix,
                                mp[1]*(1.f-mix) + (acc[mt][nt][1]+by)*mix);
            }
            if (ml+8 < rows) {
                int r = g_rowperm[start + ml + 8];
                float mix = g_mix[r & (SEQ-1)];
                const float* mp = g_main + (size_t)r*DIM + col;
                *(float2*)(out + (size_t)r*DIM + col) =
                    make_float2(mp[0]*(1.f-mix) + (acc[mt][nt][2]+bx)*mix,
                                mp[1]*(1.f-mix) + (acc[mt][nt][3]+by)*mix);
            }
        }
    }
}

// ---------------- launch ----------------
extern "C" void kernel_launch(void* const* d_in, const int* in_sizes, int n_in,
                              void* d_out, int out_size) {
    const float* x      = (const float*)d_in[0];
    const int*   levels = (const int*)  d_in[1];
    const float* gamma  = (const float*)d_in[2];
    const float* beta   = (const float*)d_in[3];
    const float* W1     = (const float*)d_in[4];
    const float* b1     = (const float*)d_in[5];
    const float* W2     = (const float*)d_in[6];
    const float* b2     = (const float*)d_in[7];
    const float* A1     = (const float*)d_in[8];
    const float* a1b    = (const float*)d_in[9];
    const float* A2     = (const float*)d_in[10];
    const float* a2b    = (const float*)d_in[11];
    const float* lmw    = (const float*)d_in[12];
    float* out = (float*)d_out;

    cudaFuncSetAttribute(k_gemm1_main,  cudaFuncAttributeMaxDynamicSharedMemorySize, SMEM_BYTES);
    cudaFuncSetAttribute(k_mid,         cudaFuncAttributeMaxDynamicSharedMemorySize, SMEM_BYTES);
    cudaFuncSetAttribute(k_gemm2_adapt, cudaFuncAttributeMaxDynamicSharedMemorySize, SMEM_BYTES);

    round_all<<<(N4_TOTAL+255)/256, 256>>>((const float4*)W1, (const float4*)W2,
                                           (const float4*)A1, (const float4*)A2);
    prep_kernel<<<1, NT>>>(levels, lmw);
    ln_kernel<<<MROWS, 256>>>(x, gamma, beta);
    k_gemm1_main <<<dim3(HID/BN, MROWS/BM), NT, SMEM_BYTES>>>(b1);
    k_mid        <<<MID_BLKS, NT, SMEM_BYTES>>>(b2, a1b);
    k_gemm2_adapt<<<dim3(DIM/BN, MAX_TILES), NT, SMEM_BYTES>>>(a2b, out);
}

// round 8
// speedup vs baseline: 1.1422x; 1.1422x over previous
#include <cuda_runtime.h>
#include <cstdint>
#include <math.h>

#define DIM   768
#define HID   3072
#define HID2  1536
#define NLEV  9
#define SEQ   2048
#define MROWS 4096
#define EPSLN 1e-5f

#define BM 128
#define BN 64
#define BK 32
#define NT 256
#define MAX_TILES 48

#define A_FLOATS (BM*BK)        /* 4096 floats, swizzled 128B rows, no pad */
#define BSTR 72                 /* B row: 64 data + 8 pad floats */
#define B_FLOATS (BK*BSTR)      /* 2304 floats */
#define STAGE (A_FLOATS + B_FLOATS)   /* 6400 floats = 25600 B */
#define NSTAGE 3
#define SMEM_BYTES (NSTAGE*STAGE*4)   /* 76800 B */

#define MID_MAIN_BLKS (12*32)   /* gemm2_main tiles: 12 n x 32 m */
#define MID_BLKS (MID_MAIN_BLKS + 24*MAX_TILES)

// ---------------- scratch (no allocations allowed) ----------------
__device__ float g_xnorm[MROWS*DIM];
__device__ float g_h[(size_t)MROWS*HID];
__device__ float g_main[MROWS*DIM];
__device__ float g_hl[MROWS*HID2];
__device__ float g_W1r[DIM*HID];
__device__ float g_W2r[HID*DIM];
__device__ float g_A1r[NLEV*DIM*HID2];
__device__ float g_A2r[NLEV*HID2*DIM];
__device__ float g_mix[SEQ];
__device__ int   g_depth[SEQ];
__device__ int   g_rowperm[MROWS];
__device__ int   g_sched_lvl[MAX_TILES];
__device__ int   g_sched_start[MAX_TILES];
__device__ int   g_sched_rows[MAX_TILES];
__device__ int   g_ntiles;

// ---------------- PTX helpers ----------------
__device__ __forceinline__ uint32_t smem_u32(const void* p) {
    return (uint32_t)__cvta_generic_to_shared(p);
}
__device__ __forceinline__ void cp16(uint32_t dst, const void* src) {
    asm volatile("cp.async.cg.shared.global [%0], [%1], 16;" :: "r"(dst), "l"(src));
}
__device__ __forceinline__ void cp_commit() {
    asm volatile("cp.async.commit_group;" ::: "memory");
}
__device__ __forceinline__ void cp_wait1() {
    asm volatile("cp.async.wait_group 1;" ::: "memory");
}
__device__ __forceinline__ void cp_wait0() {
    asm volatile("cp.async.wait_group 0;" ::: "memory");
}
__device__ __forceinline__ uint32_t f2tf32(float x) {
    uint32_t r;
    asm("cvt.rna.tf32.f32 %0, %1;" : "=r"(r) : "f"(x));
    return r;
}
__device__ __forceinline__ float round_tf32f(float x) {
    return __uint_as_float(f2tf32(x));
}
__device__ __forceinline__ void ldsm_x4(uint32_t& r0, uint32_t& r1, uint32_t& r2, uint32_t& r3,
                                        uint32_t addr) {
    asm volatile("ldmatrix.sync.aligned.m8n8.x4.shared.b16 {%0,%1,%2,%3}, [%4];"
                 : "=r"(r0), "=r"(r1), "=r"(r2), "=r"(r3) : "r"(addr));
}
__device__ __forceinline__ void mma_tf32(float& c0, float& c1, float& c2, float& c3,
                                         uint32_t a0, uint32_t a1, uint32_t a2, uint32_t a3,
                                         uint32_t b0, uint32_t b1) {
    asm volatile(
        "mma.sync.aligned.m16n8k8.row.col.f32.tf32.tf32.f32 "
        "{%0,%1,%2,%3}, {%4,%5,%6,%7}, {%8,%9}, {%0,%1,%2,%3};"
        : "+f"(c0), "+f"(c1), "+f"(c2), "+f"(c3)
        : "r"(a0), "r"(a1), "r"(a2), "r"(a3), "r"(b0), "r"(b1));
}

// ---------------- weight rounding: all four weight tensors in one launch ----------------
#define N4_W (DIM*HID/4)
#define N4_A (NLEV*DIM*HID2/4)
#define N4_TOTAL (2*N4_W + 2*N4_A)
__global__ void __launch_bounds__(256) round_all(const float4* __restrict__ W1,
                                                 const float4* __restrict__ W2,
                                                 const float4* __restrict__ A1,
                                                 const float4* __restrict__ A2) {
    int i = blockIdx.x*256 + threadIdx.x;
    if (i >= N4_TOTAL) return;
    const float4* src; float4* dst;
    if (i < N4_W)            { src = W1 + i;                dst = (float4*)g_W1r + i; }
    else if (i < 2*N4_W)     { src = W2 + (i - N4_W);       dst = (float4*)g_W2r + (i - N4_W); }
    else if (i < 2*N4_W+N4_A){ src = A1 + (i - 2*N4_W);     dst = (float4*)g_A1r + (i - 2*N4_W); }
    else                     { src = A2 + (i - 2*N4_W-N4_A);dst = (float4*)g_A2r + (i - 2*N4_W-N4_A); }
    float4 v = *src;
    v.x = round_tf32f(v.x); v.y = round_tf32f(v.y);
    v.z = round_tf32f(v.z); v.w = round_tf32f(v.w);
    *dst = v;
}

// ---------------- prep: depth clip, counting sort, tile schedule, mix ----------------
__global__ void prep_kernel(const int* __restrict__ levels, const float* __restrict__ lmw) {
    __shared__ int cnt[NLEV];
    __shared__ int cursor[NLEV];
    __shared__ float denom_sh;
    int t = threadIdx.x;
    if (t < NLEV) cnt[t] = 0;
    __syncthreads();
    for (int s = t; s < SEQ; s += NT) {
        int d = levels[s*4];
        d = min(max(d, 0), NLEV-1);
        g_depth[s] = d;
        atomicAdd(&cnt[d], 1);
    }
    __syncthreads();
    if (t == 0) {
        int o = 0, tile = 0;
        float denom = 0.f;
        for (int l = 0; l < NLEV; ++l) {
            cursor[l] = o;
            int rows = 2*cnt[l];
            int nt2 = (rows + BM - 1)/BM;
            for (int i = 0; i < nt2 && tile < MAX_TILES; ++i) {
                g_sched_lvl[tile]   = l;
                g_sched_start[tile] = o + i*BM;
                g_sched_rows[tile]  = min(BM, rows - i*BM);
                ++tile;
            }
            o += rows;
            denom += (float)cnt[l] * expf(lmw[l]);
        }
        for (int i = tile; i < MAX_TILES; ++i) g_sched_rows[i] = 0;
        g_ntiles = tile;
        denom_sh = denom;
    }
    __syncthreads();
    for (int r = t; r < MROWS; r += NT) {
        int s = r & (SEQ-1);
        int d = g_depth[s];
        int pos = atomicAdd(&cursor[d], 1);
        g_rowperm[pos] = r;
    }
    float denom = denom_sh;
    for (int s = t; s < SEQ; s += NT)
        g_mix[s] = expf(lmw[g_depth[s]]) / denom;
}

// ---------------- layernorm (writes tf32-rounded output) ----------------
__global__ void __launch_bounds__(256) ln_kernel(const float* __restrict__ x,
                                                 const float* __restrict__ gamma,
                                                 const float* __restrict__ beta) {
    int row = blockIdx.x;
    int t = threadIdx.x;
    const float* xr = x + (size_t)row*DIM;
    float v0 = xr[t], v1 = xr[t+256], v2 = xr[t+512];
    float s  = v0+v1+v2;
    float sq = v0*v0 + v1*v1 + v2*v2;
    __shared__ float red0[8], red1[8], mv[2];
#pragma unroll
    for (int o = 16; o > 0; o >>= 1) {
        s  += __shfl_xor_sync(0xffffffffu, s,  o);
        sq += __shfl_xor_sync(0xffffffffu, sq, o);
    }
    int wid = t >> 5, lid = t & 31;
    if (lid == 0) { red0[wid] = s; red1[wid] = sq; }
    __syncthreads();
    if (t == 0) {
        float S = 0.f, SQ = 0.f;
#pragma unroll
        for (int i = 0; i < 8; ++i) { S += red0[i]; SQ += red1[i]; }
        float mean = S * (1.0f/DIM);
        float var  = SQ * (1.0f/DIM) - mean*mean;
        mv[0] = mean; mv[1] = rsqrtf(var + EPSLN);
    }
    __syncthreads();
    float mean = mv[0], inv = mv[1];
    float* o = g_xnorm + (size_t)row*DIM;
    o[t]     = round_tf32f((v0-mean)*inv*gamma[t]     + beta[t]);
    o[t+256] = round_tf32f((v1-mean)*inv*gamma[t+256] + beta[t+256]);
    o[t+512] = round_tf32f((v2-mean)*inv*gamma[t+512] + beta[t+512]);
}

// ---------------- chunk loader: A swizzled 128B rows (gathered), B [k][72] ----------------
__device__ __forceinline__ void load_chunk(const float* __restrict__ A, int lda,
                                           const float* __restrict__ B, int ldb,
                                           int n0, int k0,
                                           const int* __restrict__ rowidx,
                                           uint32_t As_b, uint32_t Bs_b) {
    int t = threadIdx.x;
    // A: 128 rows x 8 c16; 2 threads/row, 4 cp16 each, XOR swizzle c16 ^= row&7
    int r = t >> 1, h = t & 1;
    int rx = r & 7;
    const float* asrc = A + (size_t)rowidx[r]*lda + k0 + h*16;
    uint32_t arow = As_b + (uint32_t)(r*128);
#pragma unroll
    for (int j = 0; j < 4; ++j) {
        int c16 = h*4 + j;
        cp16(arow + (uint32_t)((c16 ^ rx) << 4), asrc + j*4);
    }
    // B: 32 rows x 16 c16 = 512 c16 over 2 iters
#pragma unroll
    for (int i = 0; i < 2; ++i) {
        int ci = t + i*NT;
        int k = ci >> 4, c16 = ci & 15;
        cp16(Bs_b + (uint32_t)((k*BSTR + c16*4) * 4),
             B + (size_t)(k0+k)*ldb + n0 + c16*4);
    }
}

// ---------------- mma mainloop: 3-stage ring, ldmatrix A (swizzled), scalar-LDS B ----------------
__device__ __forceinline__ void mma_mainloop(const float* __restrict__ A, int lda,
                                             const float* __restrict__ B, int ldb,
                                             int K, int n0,
                                             const int* __restrict__ rowidx,
                                             float* smem, float acc[2][4][4]) {
    int t = threadIdx.x;
    int wid = t >> 5, lane = t & 31;
    int wm = wid >> 1, wn = wid & 1;
    int qid = lane >> 2, qtr = lane & 3;

    // per-lane A ldmatrix geometry
    int l8 = lane & 7, lhi = (lane >> 3) & 1, lk = lane >> 4;   // lk in {0,1}
    uint32_t a_rowoff[2]; int a_rx[2];
#pragma unroll
    for (int mt = 0; mt < 2; ++mt) {
        int row = wm*32 + mt*16 + lhi*8 + l8;
        a_rowoff[mt] = (uint32_t)(row * 128);
        a_rx[mt] = row & 7;
    }

    uint32_t sm_b = smem_u32(smem);
    int nch = K / BK;
    load_chunk(A, lda, B, ldb, n0, 0,  rowidx, sm_b,            sm_b + A_FLOATS*4);
    cp_commit();
    load_chunk(A, lda, B, ldb, n0, BK, rowidx, sm_b + STAGE*4,  sm_b + STAGE*4 + A_FLOATS*4);
    cp_commit();

    for (int c = 0; c < nch; ++c) {
        cp_wait1();
        __syncthreads();
        uint32_t st_b = sm_b + (uint32_t)((c % NSTAGE) * STAGE * 4);
        const float* Bb = smem + (c % NSTAGE)*STAGE + A_FLOATS;
#pragma unroll
        for (int ks = 0; ks < 4; ++ks) {
            uint32_t af[2][4], bf[4][2];
#pragma unroll
            for (int mt = 0; mt < 2; ++mt) {
                int c16 = 2*ks + lk;
                ldsm_x4(af[mt][0], af[mt][1], af[mt][2], af[mt][3],
                        st_b + a_rowoff[mt] + (uint32_t)((c16 ^ a_rx[mt]) << 4));
            }
            int k0 = ks * 8;
#pragma unroll
            for (int nt = 0; nt < 4; ++nt) {
                int cc = wn*32 + nt*8 + qid;
                bf[nt][0] = __float_as_uint(Bb[(k0 + qtr    )*BSTR + cc]);
                bf[nt][1] = __float_as_uint(Bb[(k0 + qtr + 4)*BSTR + cc]);
            }
#pragma unroll
            for (int mt = 0; mt < 2; ++mt)
#pragma unroll
                for (int nt = 0; nt < 4; ++nt)
                    mma_tf32(acc[mt][nt][0], acc[mt][nt][1],
                             acc[mt][nt][2], acc[mt][nt][3],
                             af[mt][0], af[mt][1], af[mt][2], af[mt][3],
                             bf[nt][0], bf[nt][1]);
        }
        if (c + 2 < nch) {
            int st = (c + 2) % NSTAGE;
            load_chunk(A, lda, B, ldb, n0, (c+2)*BK, rowidx,
                       sm_b + (uint32_t)(st*STAGE*4),
                       sm_b + (uint32_t)(st*STAGE*4) + A_FLOATS*4);
        }
        cp_commit();   // uniform group count (empty at tail)
    }
}

__device__ __forceinline__ float gelu_exact(float v) {
    return 0.5f * v * (1.0f + erff(v * 0.70710678118654752f));
}

// ---------------- main MLP GEMM1: h = round(gelu(xnorm @ W1 + b1)) ----------------
__global__ void __launch_bounds__(NT, 3) k_gemm1_main(const float* __restrict__ b1) {
    extern __shared__ float smem[];
    __shared__ int s_row[BM];
    int t = threadIdx.x;
    int m0 = blockIdx.y * BM, n0 = blockIdx.x * BN;
    if (t < BM) s_row[t] = m0 + t;
    __syncthreads();
    float acc[2][4][4] = {};
    mma_mainloop(g_xnorm, DIM, g_W1r, HID, DIM, n0, s_row, smem, acc);
    int wid = t >> 5, lane = t & 31;
    int wm = wid >> 1, wn = wid & 1, qid = lane >> 2, qtr = lane & 3;
#pragma unroll
    for (int mt = 0; mt < 2; ++mt) {
        int r0 = m0 + wm*32 + mt*16 + qid;
#pragma unroll
        for (int nt = 0; nt < 4; ++nt) {
            int col = n0 + wn*32 + nt*8 + qtr*2;
            float bx = b1[col], by = b1[col+1];
            *(float2*)(g_h + (size_t)r0*HID + col) =
                make_float2(round_tf32f(gelu_exact(acc[mt][nt][0]+bx)),
                            round_tf32f(gelu_exact(acc[mt][nt][1]+by)));
            *(float2*)(g_h + (size_t)(r0+8)*HID + col) =
                make_float2(round_tf32f(gelu_exact(acc[mt][nt][2]+bx)),
                            round_tf32f(gelu_exact(acc[mt][nt][3]+by)));
        }
    }
}

// ---------------- fused mid kernel: gemm2_main tiles + gemm1_adapt tiles ----------------
__global__ void __launch_bounds__(NT, 3) k_mid(const float* __restrict__ b2,
                                               const float* __restrict__ a1b) {
    extern __shared__ float smem[];
    __shared__ int s_row[BM];
    int t = threadIdx.x;
    int bid = blockIdx.x;
    int wid = t >> 5, lane = t & 31;
    int wm = wid >> 1, wn = wid & 1, qid = lane >> 2, qtr = lane & 3;

    if (bid < MID_MAIN_BLKS) {
        // ---- main = g_h @ W2r + b2 ----
        int m0 = (bid / 12) * BM, n0 = (bid % 12) * BN;
        if (t < BM) s_row[t] = m0 + t;
        __syncthreads();
        float acc[2][4][4] = {};
        mma_mainloop(g_h, HID, g_W2r, DIM, HID, n0, s_row, smem, acc);
#pragma unroll
        for (int mt = 0; mt < 2; ++mt) {
            int r0 = m0 + wm*32 + mt*16 + qid;
#pragma unroll
            for (int nt = 0; nt < 4; ++nt) {
                int col = n0 + wn*32 + nt*8 + qtr*2;
                float bx = b2[col], by = b2[col+1];
                *(float2*)(g_main + (size_t)r0*DIM + col) =
                    make_float2(acc[mt][nt][0]+bx, acc[mt][nt][1]+by);
                *(float2*)(g_main + (size_t)(r0+8)*DIM + col) =
                    make_float2(acc[mt][nt][2]+bx, acc[mt][nt][3]+by);
            }
        }
    } else {
        // ---- hl = round(relu(xnorm[perm] @ A1r[lvl] + a1b[lvl])) ----
        int b2i = bid - MID_MAIN_BLKS;
        int tile = b2i / 24;
        if (tile >= g_ntiles) return;
        int n0 = (b2i % 24) * BN;
        int lvl = g_sched_lvl[tile], start = g_sched_start[tile], rows = g_sched_rows[tile];
        if (t < BM) s_row[t] = g_rowperm[start + min(t, rows-1)];
        __syncthreads();
        float acc[2][4][4] = {};
        mma_mainloop(g_xnorm, DIM, g_A1r + (size_t)lvl*DIM*HID2, HID2, DIM, n0,
                     s_row, smem, acc);
        const float* bb = a1b + (size_t)lvl*HID2;
#pragma unroll
        for (int mt = 0; mt < 2; ++mt) {
            int ml = wm*32 + mt*16 + qid;
#pragma unroll
            for (int nt = 0; nt < 4; ++nt) {
                int col = n0 + wn*32 + nt*8 + qtr*2;
                float bx = bb[col], by = bb[col+1];
                if (ml < rows)
                    *(float2*)(g_hl + (size_t)(start+ml)*HID2 + col) =
                        make_float2(round_tf32f(fmaxf(acc[mt][nt][0]+bx, 0.f)),
                                    round_tf32f(fmaxf(acc[mt][nt][1]+by, 0.f)));
                if (ml+8 < rows)
                    *(float2*)(g_hl + (size_t)(start+ml+8)*HID2 + col) =
                        make_float2(round_tf32f(fmaxf(acc[mt][nt][2]+bx, 0.f)),
                                    round_tf32f(fmaxf(acc[mt][nt][3]+by, 0.f)));
            }
        }
    }
}

// ---------------- adapter GEMM2 + final combine ----------------
__global__ void __launch_bounds__(NT, 3) k_gemm2_adapt(const float* __restrict__ a2b,
                                                       float* __restrict__ out) {
    if ((int)blockIdx.y >= g_ntiles) return;
    extern __shared__ float smem[];
    __shared__ int s_row[BM];
    int t = threadIdx.x;
    int tile = blockIdx.y;
    int lvl = g_sched_lvl[tile], start = g_sched_start[tile], rows = g_sched_rows[tile];
    int n0 = blockIdx.x * BN;
    if (t < BM) s_row[t] = min(start + t, MROWS-1);   // g_hl rows are compacted
    __syncthreads();
    float acc[2][4][4] = {};
    mma_mainloop(g_hl, HID2, g_A2r + (size_t)lvl*HID2*DIM, DIM, HID2, n0, s_row, smem, acc);
    int wid = t >> 5, lane = t & 31;
    int wm = wid >> 1, wn = wid & 1, qid = lane >> 2, qtr = lane & 3;
    const float* bb = a2b + (size_t)lvl*DIM;
#pragma unroll
    for (int mt = 0; mt < 2; ++mt) {
        int ml = wm*32 + mt*16 + qid;
#pragma unroll
        for (int nt = 0; nt < 4; ++nt) {
            int col = n0 + wn*32 + nt*8 + qtr*2;
            float bx = bb[col], by = bb[col+1];
            if (ml < rows) {
                int r = g_rowperm[start + ml];
                float mix = g_mix[r & (SEQ-1)];
                const float* mp = g_main + (size_t)r*DIM + col;
                *(float2*)(out + (size_t)r*DIM + col) =
                    make_float2(mp[0]*(1.f-mix) + (acc[mt][nt][0]+bx)*mix,
                                mp[1]*(1.f-mix) + (acc[mt][nt][1]+by)*mix);
            }
            if (ml+8 < rows) {
                int r = g_rowperm[start + ml + 8];
                float mix = g_mix[r & (SEQ-1)];
                const float* mp = g_main + (size_t)r*DIM + col;
                *(float2*)(out + (size_t)r*DIM + col) =
                    make_float2(mp[0]*(1.f-mix) + (acc[mt][nt][2]+bx)*mix,
                                mp[1]*(1.f-mix) + (acc[mt][nt][3]+by)*mix);
            }
        }
    }
}

// ---------------- launch ----------------
extern "C" void kernel_launch(void* const* d_in, const int* in_sizes, int n_in,
                              void* d_out, int out_size) {
    const float* x      = (const float*)d_in[0];
    const int*   levels = (const int*)  d_in[1];
    const float* gamma  = (const float*)d_in[2];
    const float* beta   = (const float*)d_in[3];
    const float* W1     = (const float*)d_in[4];
    const float* b1     = (const float*)d_in[5];
    const float* W2     = (const float*)d_in[6];
    const float* b2     = (const float*)d_in[7];
    const float* A1     = (const float*)d_in[8];
    const float* a1b    = (const float*)d_in[9];
    const float* A2     = (const float*)d_in[10];
    const float* a2b    = (const float*)d_in[11];
    const float* lmw    = (const float*)d_in[12];
    float* out = (float*)d_out;

    cudaFuncSetAttribute(k_gemm1_main,  cudaFuncAttributeMaxDynamicSharedMemorySize, SMEM_BYTES);
    cudaFuncSetAttribute(k_mid,         cudaFuncAttributeMaxDynamicSharedMemorySize, SMEM_BYTES);
    cudaFuncSetAttribute(k_gemm2_adapt, cudaFuncAttributeMaxDynamicSharedMemorySize, SMEM_BYTES);

    round_all<<<(N4_TOTAL+255)/256, 256>>>((const float4*)W1, (const float4*)W2,
                                           (const float4*)A1, (const float4*)A2);
    prep_kernel<<<1, NT>>>(levels, lmw);
    ln_kernel<<<MROWS, 256>>>(x, gamma, beta);
    k_gemm1_main <<<dim3(HID/BN, MROWS/BM), NT, SMEM_BYTES>>>(b1);
    k_mid        <<<MID_BLKS, NT, SMEM_BYTES>>>(b2, a1b);
    k_gemm2_adapt<<<dim3(DIM/BN, MAX_TILES), NT, SMEM_BYTES>>>(a2b, out);
}

// round 9
// speedup vs baseline: 1.4845x; 1.2997x over previous
#include <cuda_runtime.h>
#include <cstdint>
#include <math.h>

#define DIM   768
#define HID   3072
#define HID2  1536
#define NLEV  9
#define SEQ   2048
#define MROWS 4096
#define EPSLN 1e-5f

#define BM 128
#define BN 128
#define BK 32
#define NT 256
#define MAX_TILES 48

#define ASTR 36    /* floats per A smem row  (bank-bijective, 16B aligned, ldmatrix-safe) */
#define BSTR 136   /* floats per B smem row */
#define ABUF (BM*ASTR)   /* 4608 floats */
#define BBUF (BK*BSTR)   /* 4352 floats */
#define STAGE (ABUF+BBUF)
#define NSTAGE 3
#define SMEM_FLOATS (NSTAGE*STAGE)
#define SMEM_BYTES  (SMEM_FLOATS*4)

#define MID_MAIN_BLKS (6*32)   /* gemm2_main tiles */
#define MID_BLKS (MID_MAIN_BLKS + 12*MAX_TILES)

// ---------------- scratch (no allocations allowed) ----------------
__device__ float g_xnorm[MROWS*DIM];
__device__ float g_h[(size_t)MROWS*HID];
__device__ float g_main[MROWS*DIM];
__device__ float g_hl[MROWS*HID2];
__device__ float g_W1r[DIM*HID];
__device__ float g_W2r[HID*DIM];
__device__ float g_A1r[NLEV*DIM*HID2];
__device__ float g_A2r[NLEV*HID2*DIM];
__device__ float g_mix[SEQ];
__device__ int   g_depth[SEQ];
__device__ int   g_rowperm[MROWS];
__device__ int   g_sched_lvl[MAX_TILES];
__device__ int   g_sched_start[MAX_TILES];
__device__ int   g_sched_rows[MAX_TILES];
__device__ int   g_ntiles;

// ---------------- PTX helpers ----------------
__device__ __forceinline__ uint32_t smem_u32(const void* p) {
    return (uint32_t)__cvta_generic_to_shared(p);
}
__device__ __forceinline__ void cp16(uint32_t dst, const void* src) {
    asm volatile("cp.async.cg.shared.global [%0], [%1], 16;" :: "r"(dst), "l"(src));
}
__device__ __forceinline__ void cp_commit() {
    asm volatile("cp.async.commit_group;" ::: "memory");
}
__device__ __forceinline__ void cp_wait1() {
    asm volatile("cp.async.wait_group 1;" ::: "memory");
}
__device__ __forceinline__ uint32_t f2tf32(float x) {
    uint32_t r;
    asm("cvt.rna.tf32.f32 %0, %1;" : "=r"(r) : "f"(x));
    return r;
}
__device__ __forceinline__ float round_tf32f(float x) {
    return __uint_as_float(f2tf32(x));
}
__device__ __forceinline__ void ldsm_x4(uint32_t& r0, uint32_t& r1, uint32_t& r2, uint32_t& r3,
                                        uint32_t addr) {
    asm volatile("ldmatrix.sync.aligned.m8n8.x4.shared.b16 {%0,%1,%2,%3}, [%4];"
                 : "=r"(r0), "=r"(r1), "=r"(r2), "=r"(r3) : "r"(addr));
}
__device__ __forceinline__ void mma_tf32(float& c0, float& c1, float& c2, float& c3,
                                         uint32_t a0, uint32_t a1, uint32_t a2, uint32_t a3,
                                         uint32_t b0, uint32_t b1) {
    asm volatile(
        "mma.sync.aligned.m16n8k8.row.col.f32.tf32.tf32.f32 "
        "{%0,%1,%2,%3}, {%4,%5,%6,%7}, {%8,%9}, {%0,%1,%2,%3};"
        : "+f"(c0), "+f"(c1), "+f"(c2), "+f"(c3)
        : "r"(a0), "r"(a1), "r"(a2), "r"(a3), "r"(b0), "r"(b1));
}

// ---------------- weight rounding: all four weight tensors in one launch ----------------
#define N4_W (DIM*HID/4)
#define N4_A (NLEV*DIM*HID2/4)
#define N4_TOTAL (2*N4_W + 2*N4_A)
__global__ void __launch_bounds__(256) round_all(const float4* __restrict__ W1,
                                                 const float4* __restrict__ W2,
                                                 const float4* __restrict__ A1,
                                                 const float4* __restrict__ A2) {
    int i = blockIdx.x*256 + threadIdx.x;
    if (i >= N4_TOTAL) return;
    const float4* src; float4* dst;
    if (i < N4_W)            { src = W1 + i;                dst = (float4*)g_W1r + i; }
    else if (i < 2*N4_W)     { src = W2 + (i - N4_W);       dst = (float4*)g_W2r + (i - N4_W); }
    else if (i < 2*N4_W+N4_A){ src = A1 + (i - 2*N4_W);     dst = (float4*)g_A1r + (i - 2*N4_W); }
    else                     { src = A2 + (i - 2*N4_W-N4_A);dst = (float4*)g_A2r + (i - 2*N4_W-N4_A); }
    float4 v = *src;
    v.x = round_tf32f(v.x); v.y = round_tf32f(v.y);
    v.z = round_tf32f(v.z); v.w = round_tf32f(v.w);
    *dst = v;
}

// ---------------- prep: depth clip, counting sort, tile schedule, mix ----------------
__global__ void prep_kernel(const int* __restrict__ levels, const float* __restrict__ lmw) {
    __shared__ int cnt[NLEV];
    __shared__ int cursor[NLEV];
    __shared__ float denom_sh;
    int t = threadIdx.x;
    if (t < NLEV) cnt[t] = 0;
    __syncthreads();
    for (int s = t; s < SEQ; s += NT) {
        int d = levels[s*4];
        d = min(max(d, 0), NLEV-1);
        g_depth[s] = d;
        atomicAdd(&cnt[d], 1);
    }
    __syncthreads();
    if (t == 0) {
        int o = 0, tile = 0;
        float denom = 0.f;
        for (int l = 0; l < NLEV; ++l) {
            cursor[l] = o;
            int rows = 2*cnt[l];
            int nt2 = (rows + BM - 1)/BM;
            for (int i = 0; i < nt2 && tile < MAX_TILES; ++i) {
                g_sched_lvl[tile]   = l;
                g_sched_start[tile] = o + i*BM;
                g_sched_rows[tile]  = min(BM, rows - i*BM);
                ++tile;
            }
            o += rows;
            denom += (float)cnt[l] * expf(lmw[l]);
        }
        for (int i = tile; i < MAX_TILES; ++i) g_sched_rows[i] = 0;
        g_ntiles = tile;
        denom_sh = denom;
    }
    __syncthreads();
    for (int r = t; r < MROWS; r += NT) {
        int s = r & (SEQ-1);
        int d = g_depth[s];
        int pos = atomicAdd(&cursor[d], 1);
        g_rowperm[pos] = r;
    }
    float denom = denom_sh;
    for (int s = t; s < SEQ; s += NT)
        g_mix[s] = expf(lmw[g_depth[s]]) / denom;
}

// ---------------- layernorm (writes tf32-rounded output) ----------------
__global__ void __launch_bounds__(256) ln_kernel(const float* __restrict__ x,
                                                 const float* __restrict__ gamma,
                                                 const float* __restrict__ beta) {
    int row = blockIdx.x;
    int t = threadIdx.x;
    const float* xr = x + (size_t)row*DIM;
    float v0 = xr[t], v1 = xr[t+256], v2 = xr[t+512];
    float s  = v0+v1+v2;
    float sq = v0*v0 + v1*v1 + v2*v2;
    __shared__ float red0[8], red1[8], mv[2];
#pragma unroll
    for (int o = 16; o > 0; o >>= 1) {
        s  += __shfl_xor_sync(0xffffffffu, s,  o);
        sq += __shfl_xor_sync(0xffffffffu, sq, o);
    }
    int wid = t >> 5, lid = t & 31;
    if (lid == 0) { red0[wid] = s; red1[wid] = sq; }
    __syncthreads();
    if (t == 0) {
        float S = 0.f, SQ = 0.f;
#pragma unroll
        for (int i = 0; i < 8; ++i) { S += red0[i]; SQ += red1[i]; }
        float mean = S * (1.0f/DIM);
        float var  = SQ * (1.0f/DIM) - mean*mean;
        mv[0] = mean; mv[1] = rsqrtf(var + EPSLN);
    }
    __syncthreads();
    float mean = mv[0], inv = mv[1];
    float* o = g_xnorm + (size_t)row*DIM;
    o[t]     = round_tf32f((v0-mean)*inv*gamma[t]     + beta[t]);
    o[t+256] = round_tf32f((v1-mean)*inv*gamma[t+256] + beta[t+256]);
    o[t+512] = round_tf32f((v2-mean)*inv*gamma[t+512] + beta[t+512]);
}

// ---------------- chunk loader (no commit inside) ----------------
__device__ __forceinline__ void load_chunk(const float* __restrict__ A, int lda,
                                           const float* __restrict__ B, int ldb,
                                           int n0, int k0,
                                           const int* __restrict__ rowidx,
                                           float* As, float* Bs) {
    int t = threadIdx.x;
#pragma unroll
    for (int i = 0; i < 4; ++i) {
        int ci = t + i*NT;
        int row = ci >> 3, seg = ci & 7;
        cp16(smem_u32(As + row*ASTR + seg*4),
             A + (size_t)rowidx[row]*lda + k0 + seg*4);
    }
#pragma unroll
    for (int i = 0; i < 4; ++i) {
        int ci = t + i*NT;
        int k = ci >> 5, ns = ci & 31;
        cp16(smem_u32(Bs + k*BSTR + ns*4),
             B + (size_t)(k0+k)*ldb + n0 + ns*4);
    }
}

// ---------------- mma mainloop: 3-stage ring + software-pipelined fragments ----------------
__device__ __forceinline__ void mma_mainloop(const float* __restrict__ A, int lda,
                                             const float* __restrict__ B, int ldb,
                                             int K, int n0,
                                             const int* __restrict__ rowidx,
                                             float* smem, float acc[4][4][4]) {
    int t = threadIdx.x;
    int wid = t >> 5, lane = t & 31;
    int wm = wid & 1, wn = wid >> 1;
    int qid = lane >> 2, qtr = lane & 3;

    // ldmatrix lane address pattern (per mt), byte offsets within A stage
    int l8 = lane & 7, lhi = (lane >> 3) & 1, lk = lane >> 4;
    uint32_t a_off[4];
#pragma unroll
    for (int mt = 0; mt < 4; ++mt) {
        int row = wm*64 + mt*16 + lhi*8 + l8;
        a_off[mt] = (uint32_t)((row*ASTR + lk*4) * 4);
    }
    int b_base0 = qtr*BSTR + wn*32 + qid;   // element offset for bf[.][0] at k0=0

    int nch = K / BK;
    load_chunk(A, lda, B, ldb, n0, 0,  rowidx, smem,           smem + ABUF);
    cp_commit();
    load_chunk(A, lda, B, ldb, n0, BK, rowidx, smem + STAGE,   smem + STAGE + ABUF);
    cp_commit();

    for (int c = 0; c < nch; ++c) {
        cp_wait1();
        __syncthreads();
        const float* Bb = smem + (c % NSTAGE)*STAGE + ABUF;
        uint32_t ab_base = smem_u32(smem + (c % NSTAGE)*STAGE);

        uint32_t af[2][4], bf[2][8];
        // prologue: fragment f=0 (ks=0, mt=0) and all bf of ks=0
        ldsm_x4(af[0][0], af[0][1], af[0][2], af[0][3], ab_base + a_off[0]);
#pragma unroll
        for (int nt = 0; nt < 4; ++nt) {
            int cc = b_base0 + nt*8;
            bf[0][nt*2  ] = __float_as_uint(Bb[cc]);
            bf[0][nt*2+1] = __float_as_uint(Bb[cc + 4*BSTR]);
        }
#pragma unroll
        for (int f = 0; f < 16; ++f) {
            const int ks = f >> 2, mt = f & 3;
            const int cur = f & 1, nxt = cur ^ 1;
            const int kb = ks & 1;
            // prefetch next A fragment (f+1)
            if (f < 15) {
                const int f1 = f + 1, ks1 = f1 >> 2, mt1 = f1 & 3;
                ldsm_x4(af[nxt][0], af[nxt][1], af[nxt][2], af[nxt][3],
                        ab_base + a_off[mt1] + (uint32_t)(ks1*32));
            }
            // prefetch next ks B fragments (at mt==0, so they land well before use)
            if (mt == 0 && ks < 3) {
                const int k0n = (ks+1)*8;
#pragma unroll
                for (int nt = 0; nt < 4; ++nt) {
                    int cc = b_base0 + k0n*BSTR + nt*8;
                    bf[kb^1][nt*2  ] = __float_as_uint(Bb[cc]);
                    bf[kb^1][nt*2+1] = __float_as_uint(Bb[cc + 4*BSTR]);
                }
            }
            // 16 MMAs for (ks, mt)
#pragma unroll
            for (int nt = 0; nt < 4; ++nt)
                mma_tf32(acc[mt][nt][0], acc[mt][nt][1],
                         acc[mt][nt][2], acc[mt][nt][3],
                         af[cur][0], af[cur][1], af[cur][2], af[cur][3],
                         bf[kb][nt*2], bf[kb][nt*2+1]);
        }
        if (c + 2 < nch) {
            int st = (c + 2) % NSTAGE;
            load_chunk(A, lda, B, ldb, n0, (c+2)*BK, rowidx,
                       smem + st*STAGE, smem + st*STAGE + ABUF);
        }
        cp_commit();   // uniform group count (empty at tail)
    }
}

__device__ __forceinline__ float gelu_exact(float v) {
    return 0.5f * v * (1.0f + erff(v * 0.70710678118654752f));
}

// ---------------- main MLP GEMM1: h = round(gelu(xnorm @ W1 + b1)) ----------------
__global__ void __launch_bounds__(NT, 2) k_gemm1_main(const float* __restrict__ b1) {
    extern __shared__ float smem[];
    __shared__ int s_row[BM];
    int t = threadIdx.x;
    int m0 = blockIdx.y * BM, n0 = blockIdx.x * BN;
    if (t < BM) s_row[t] = m0 + t;
    __syncthreads();
    float acc[4][4][4] = {};
    mma_mainloop(g_xnorm, DIM, g_W1r, HID, DIM, n0, s_row, smem, acc);
    int wid = t >> 5, lane = t & 31;
    int wm = wid & 1, wn = wid >> 1, qid = lane >> 2, qtr = lane & 3;
#pragma unroll
    for (int mt = 0; mt < 4; ++mt) {
        int r0 = m0 + wm*64 + mt*16 + qid;
#pragma unroll
        for (int nt = 0; nt < 4; ++nt) {
            int col = n0 + wn*32 + nt*8 + qtr*2;
            float bx = b1[col], by = b1[col+1];
            *(float2*)(g_h + (size_t)r0*HID + col) =
                make_float2(round_tf32f(gelu_exact(acc[mt][nt][0]+bx)),
                            round_tf32f(gelu_exact(acc[mt][nt][1]+by)));
            *(float2*)(g_h + (size_t)(r0+8)*HID + col) =
                make_float2(round_tf32f(gelu_exact(acc[mt][nt][2]+bx)),
                            round_tf32f(gelu_exact(acc[mt][nt][3]+by)));
        }
    }
}

// ---------------- fused mid kernel: gemm2_main tiles + gemm1_adapt tiles ----------------
__global__ void __launch_bounds__(NT, 2) k_mid(const float* __restrict__ b2,
                                               const float* __restrict__ a1b) {
    extern __shared__ float smem[];
    __shared__ int s_row[BM];
    int t = threadIdx.x;
    int bid = blockIdx.x;
    int wid = t >> 5, lane = t & 31;
    int wm = wid & 1, wn = wid >> 1, qid = lane >> 2, qtr = lane & 3;

    if (bid < MID_MAIN_BLKS) {
        // ---- main = g_h @ W2r + b2 ----
        int m0 = (bid / 6) * BM, n0 = (bid % 6) * BN;
        if (t < BM) s_row[t] = m0 + t;
        __syncthreads();
        float acc[4][4][4] = {};
        mma_mainloop(g_h, HID, g_W2r, DIM, HID, n0, s_row, smem, acc);
#pragma unroll
        for (int mt = 0; mt < 4; ++mt) {
            int r0 = m0 + wm*64 + mt*16 + qid;
#pragma unroll
            for (int nt = 0; nt < 4; ++nt) {
                int col = n0 + wn*32 + nt*8 + qtr*2;
                float bx = b2[col], by = b2[col+1];
                *(float2*)(g_main + (size_t)r0*DIM + col) =
                    make_float2(acc[mt][nt][0]+bx, acc[mt][nt][1]+by);
                *(float2*)(g_main + (size_t)(r0+8)*DIM + col) =
                    make_float2(acc[mt][nt][2]+bx, acc[mt][nt][3]+by);
            }
        }
    } else {
        // ---- hl = round(relu(xnorm[perm] @ A1r[lvl] + a1b[lvl])) ----
        int b2i = bid - MID_MAIN_BLKS;
        int tile = b2i / 12;
        if (tile >= g_ntiles) return;
        int n0 = (b2i % 12) * BN;
        int lvl = g_sched_lvl[tile], start = g_sched_start[tile], rows = g_sched_rows[tile];
        if (t < BM) s_row[t] = g_rowperm[start + min(t, rows-1)];
        __syncthreads();
        float acc[4][4][4] = {};
        mma_mainloop(g_xnorm, DIM, g_A1r + (size_t)lvl*DIM*HID2, HID2, DIM, n0,
                     s_row, smem, acc);
        const float* bb = a1b + (size_t)lvl*HID2;
#pragma unroll
        for (int mt = 0; mt < 4; ++mt) {
            int ml = wm*64 + mt*16 + qid;
#pragma unroll
            for (int nt = 0; nt < 4; ++nt) {
                int col = n0 + wn*32 + nt*8 + qtr*2;
                float bx = bb[col], by = bb[col+1];
                if (ml < rows)
                    *(float2*)(g_hl + (size_t)(start+ml)*HID2 + col) =
                        make_float2(round_tf32f(fmaxf(acc[mt][nt][0]+bx, 0.f)),
                                    round_tf32f(fmaxf(acc[mt][nt][1]+by, 0.f)));
                if (ml+8 < rows)
                    *(float2*)(g_hl + (size_t)(start+ml+8)*HID2 + col) =
                        make_float2(round_tf32f(fmaxf(acc[mt][nt][2]+bx, 0.f)),
                                    round_tf32f(fmaxf(acc[mt][nt][3]+by, 0.f)));
            }
        }
    }
}

// ---------------- adapter GEMM2 + final combine ----------------
__global__ void __launch_bounds__(NT, 2) k_gemm2_adapt(const float* __restrict__ a2b,
                                                       float* __restrict__ out) {
    if ((int)blockIdx.y >= g_ntiles) return;
    extern __shared__ float smem[];
    __shared__ int s_row[BM];
    int t = threadIdx.x;
    int tile = blockIdx.y;
    int lvl = g_sched_lvl[tile], start = g_sched_start[tile], rows = g_sched_rows[tile];
    int n0 = blockIdx.x * BN;
    if (t < BM) s_row[t] = min(start + t, MROWS-1);   // g_hl rows are compacted
    __syncthreads();
    float acc[4][4][4] = {};
    mma_mainloop(g_hl, HID2, g_A2r + (size_t)lvl*HID2*DIM, DIM, HID2, n0, s_row, smem, acc);
    int wid = t >> 5, lane = t & 31;
    int wm = wid & 1, wn = wid >> 1, qid = lane >> 2, qtr = lane & 3;
    const float* bb = a2b + (size_t)lvl*DIM;
#pragma unroll
    for (int mt = 0; mt < 4; ++mt) {
        int ml = wm*64 + mt*16 + qid;
#pragma unroll
        for (int nt = 0; nt < 4; ++nt) {
            int col = n0 + wn*32 + nt*8 + qtr*2;
            float bx = bb[col], by = bb[col+1];
            if (ml < rows) {
                int r = g_rowperm[start + ml];
                float mix = g_mix[r & (SEQ-1)];
                const float* mp = g_main + (size_t)r*DIM + col;
                *(float2*)(out + (size_t)r*DIM + col) =
                    make_float2(mp[0]*(1.f-mix) + (acc[mt][nt][0]+bx)*mix,
                                mp[1]*(1.f-mix) + (acc[mt][nt][1]+by)*mix);
            }
            if (ml+8 < rows) {
                int r = g_rowperm[start + ml + 8];
                float mix = g_mix[r & (SEQ-1)];
                const float* mp = g_main + (size_t)r*DIM + col;
                *(float2*)(out + (size_t)r*DIM + col) =
                    make_float2(mp[0]*(1.f-mix) + (acc[mt][nt][2]+bx)*mix,
                                mp[1]*(1.f-mix) + (acc[mt][nt][3]+by)*mix);
            }
        }
    }
}

// ---------------- launch ----------------
extern "C" void kernel_launch(void* const* d_in, const int* in_sizes, int n_in,
                              void* d_out, int out_size) {
    const float* x      = (const float*)d_in[0];
    const int*   levels = (const int*)  d_in[1];
    const float* gamma  = (const float*)d_in[2];
    const float* beta   = (const float*)d_in[3];
    const float* W1     = (const float*)d_in[4];
    const float* b1     = (const float*)d_in[5];
    const float* W2     = (const float*)d_in[6];
    const float* b2     = (const float*)d_in[7];
    const float* A1     = (const float*)d_in[8];
    const float* a1b    = (const float*)d_in[9];
    const float* A2     = (const float*)d_in[10];
    const float* a2b    = (const float*)d_in[11];
    const float* lmw    = (const float*)d_in[12];
    float* out = (float*)d_out;

    cudaFuncSetAttribute(k_gemm1_main,  cudaFuncAttributeMaxDynamicSharedMemorySize, SMEM_BYTES);
    cudaFuncSetAttribute(k_mid,         cudaFuncAttributeMaxDynamicSharedMemorySize, SMEM_BYTES);
    cudaFuncSetAttribute(k_gemm2_adapt, cudaFuncAttributeMaxDynamicSharedMemorySize, SMEM_BYTES);

    round_all<<<(N4_TOTAL+255)/256, 256>>>((const float4*)W1, (const float4*)W2,
                                           (const float4*)A1, (const float4*)A2);
    prep_kernel<<<1, NT>>>(levels, lmw);
    ln_kernel<<<MROWS, 256>>>(x, gamma, beta);
    k_gemm1_main <<<dim3(HID/BN, MROWS/BM), NT, SMEM_BYTES>>>(b1);
    k_mid        <<<MID_BLKS, NT, SMEM_BYTES>>>(b2, a1b);
    k_gemm2_adapt<<<dim3(DIM/BN, MAX_TILES), NT, SMEM_BYTES>>>(a2b, out);
}